// round 7
// baseline (speedup 1.0000x reference)
#include <cuda_runtime.h>

// ---------------------------------------------------------------------------
// MyModel_87522843559014: LSTM(B=256,T=512,F=128,H=256) + MLP head
//   reset -> xz_gemm -> dummy -> lstm (ncu captures 4th launch) -> head
//   lstm: 128 persistent blocks x 512 threads, 16 groups x 8 blocks.
//   k-pair-major smem, conflict-free LDS; K split in quarters across warps.
// ---------------------------------------------------------------------------

typedef unsigned long long ull;

__device__ float g_xz[512u * 256u * 1024u];   // [T][B][4H] fp32
__device__ float g_h[2][256][256];            // double-buffered hidden state
__device__ unsigned g_cnt[16 * 32];           // counters padded to 128B lines

__global__ void reset_kernel() {
    if (threadIdx.x < 16) g_cnt[threadIdx.x * 32] = 0u;
}
__global__ void dummy_kernel() {}

// ---------------- f32x2 helpers ----------------------------------------------
__device__ __forceinline__ ull fma2(ull a, ull b, ull c) {
    ull d;
    asm("fma.rn.f32x2 %0, %1, %2, %3;" : "=l"(d) : "l"(a), "l"(b), "l"(c));
    return d;
}
__device__ __forceinline__ ull dup2(float x) {
    ull r;
    asm("mov.b64 %0, {%1, %1};" : "=l"(r) : "f"(x));
    return r;
}
__device__ __forceinline__ float lo32(ull v) { return __uint_as_float((unsigned)v); }
__device__ __forceinline__ float hi32(ull v) { return __uint_as_float((unsigned)(v >> 32)); }
__device__ __forceinline__ ull pack2(float lo, float hi) {
    ull r;
    asm("mov.b64 %0, {%1, %2};" : "=l"(r) : "f"(lo), "f"(hi));
    return r;
}

// ---------------- per-group barrier (8 blocks, padded counter) ----------------
__device__ __forceinline__ void group_wait(int grp, unsigned target) {
    __threadfence();
    __syncthreads();
    if (threadIdx.x == 0) {
        unsigned* ctr = &g_cnt[grp * 32];
        atomicAdd(ctr, 1u);
        unsigned v;
        do {
            asm volatile("ld.global.acquire.gpu.u32 %0, [%1];"
                         : "=r"(v) : "l"(ctr) : "memory");
        } while (v < target);
    }
    __syncthreads();
}

// ---------------- input projection GEMM (f32x2) -------------------------------
__global__ void __launch_bounds__(256, 2)
xz_gemm_kernel(const float* __restrict__ x, const float* __restrict__ kern) {
    __shared__ float As[8][132];
    __shared__ float Bs[8][132];

    const int tid = threadIdx.x;
    const int nb = blockIdx.x;
    const int mb = blockIdx.y;
    const int m0 = mb * 128, n0 = nb * 128;

    const int lrow = tid >> 1;
    const int lk4  = (tid & 1) * 4;
    const int m    = m0 + lrow;
    const int tt   = m >> 8;
    const int bb   = m & 255;
    const float* xrow = x + ((size_t)bb * 512 + tt) * 128;

    const int bk = tid >> 5;
    const int bn = (tid & 31) * 4;

    const int tm = (tid >> 4) * 8;
    const int tn = (tid & 15) * 8;

    ull acc2[4][8];
#pragma unroll
    for (int i = 0; i < 4; i++)
#pragma unroll
        for (int j = 0; j < 8; j++) acc2[i][j] = 0ull;

    for (int k0 = 0; k0 < 128; k0 += 8) {
        float4 av = *(const float4*)(xrow + k0 + lk4);
        float4 bv = *(const float4*)(kern + (size_t)(k0 + bk) * 1024 + n0 + bn);
        __syncthreads();
        As[lk4 + 0][lrow] = av.x;
        As[lk4 + 1][lrow] = av.y;
        As[lk4 + 2][lrow] = av.z;
        As[lk4 + 3][lrow] = av.w;
        *(float4*)&Bs[bk][bn] = bv;
        __syncthreads();
#pragma unroll
        for (int kk = 0; kk < 8; kk++) {
            ulonglong2 a0 = *(const ulonglong2*)&As[kk][tm];
            ulonglong2 a1 = *(const ulonglong2*)&As[kk][tm + 4];
            ull ap[4] = {a0.x, a0.y, a1.x, a1.y};
            float4 b0 = *(const float4*)&Bs[kk][tn];
            float4 b1 = *(const float4*)&Bs[kk][tn + 4];
            {
                ull bd0 = dup2(b0.x), bd1 = dup2(b0.y), bd2 = dup2(b0.z), bd3 = dup2(b0.w);
#pragma unroll
                for (int i = 0; i < 4; i++) {
                    acc2[i][0] = fma2(ap[i], bd0, acc2[i][0]);
                    acc2[i][1] = fma2(ap[i], bd1, acc2[i][1]);
                    acc2[i][2] = fma2(ap[i], bd2, acc2[i][2]);
                    acc2[i][3] = fma2(ap[i], bd3, acc2[i][3]);
                }
            }
            {
                ull bd4 = dup2(b1.x), bd5 = dup2(b1.y), bd6 = dup2(b1.z), bd7 = dup2(b1.w);
#pragma unroll
                for (int i = 0; i < 4; i++) {
                    acc2[i][4] = fma2(ap[i], bd4, acc2[i][4]);
                    acc2[i][5] = fma2(ap[i], bd5, acc2[i][5]);
                    acc2[i][6] = fma2(ap[i], bd6, acc2[i][6]);
                    acc2[i][7] = fma2(ap[i], bd7, acc2[i][7]);
                }
            }
        }
    }

#pragma unroll
    for (int i2 = 0; i2 < 4; i2++) {
        float* d0 = g_xz + (size_t)(m0 + tm + 2 * i2) * 1024 + n0 + tn;
        float* d1 = d0 + 1024;
        *(float4*)(d0 + 0) = make_float4(lo32(acc2[i2][0]), lo32(acc2[i2][1]),
                                         lo32(acc2[i2][2]), lo32(acc2[i2][3]));
        *(float4*)(d0 + 4) = make_float4(lo32(acc2[i2][4]), lo32(acc2[i2][5]),
                                         lo32(acc2[i2][6]), lo32(acc2[i2][7]));
        *(float4*)(d1 + 0) = make_float4(hi32(acc2[i2][0]), hi32(acc2[i2][1]),
                                         hi32(acc2[i2][2]), hi32(acc2[i2][3]));
        *(float4*)(d1 + 4) = make_float4(hi32(acc2[i2][4]), hi32(acc2[i2][5]),
                                         hi32(acc2[i2][6]), hi32(acc2[i2][7]));
    }
}

// ---------------- fast activations -------------------------------------------
__device__ __forceinline__ float sigf(float x)     { return 1.f / (1.f + __expf(-x)); }
__device__ __forceinline__ float tanhfast(float x) { return 2.f / (1.f + __expf(-2.f * x)) - 1.f; }

// ---------------- persistent LSTM kernel -------------------------------------
// 16 groups x 8 blocks, 512 threads/block. Group = 16 batches; block jt owns
// 128 gate-cols. smem layouts as R6 (k-pair-major, conflict-free).
// Warp wid (16): kq = wid&3 (k-quarter, 32 kpairs), bhalf=(wid>>2)&1, chalf=wid>>3.
// Lane: cg=lane&15, bgroup=lane>>4. Thread: 4 batches x 4 cols x 64 k.
// Four partial arrays zs[kq]; summed in the gate phase.
#define WST 130
#define HST 18
__global__ void __launch_bounds__(512, 1)
lstm_kernel(const float* __restrict__ rkernel) {
    extern __shared__ ull smem[];
    ull*   wq  = smem;                          // 128*130 ull = 133120 B
    ull*   hq  = wq + 128 * WST;                // 128*18 ull  =  18432 B
    float* zs  = (float*)(hq + 128 * HST);      // 4*[128][17] =  34816 B
    float* c_s = zs + 4 * 128 * 17;             // [512] f     =   2048 B

    const int tid = threadIdx.x;
    const int grp = blockIdx.x >> 3;    // 0..15
    const int jt  = blockIdx.x & 7;     // 0..7
    const int bbase = grp * 16, jbase = jt * 32;

    {   // init c=0 and our slice of h0 (one (b,j) pair per thread)
        int bb = tid >> 5, jj = tid & 31;
        c_s[tid] = 0.f;
        g_h[0][bbase + bb][jbase + jj] = 0.f;
    }
    // weights k-pair-major: wq[kp*WST + c] = (rk[2kp][col], rk[2kp+1][col])
    for (int idx = tid; idx < 128 * 128; idx += 512) {
        int c = idx & 127, kp = idx >> 7;
        int col = (c >> 5) * 256 + jbase + (c & 31);
        float wlo = rkernel[(2 * kp) * 1024 + col];
        float whi = rkernel[(2 * kp + 1) * 1024 + col];
        wq[kp * WST + c] = pack2(wlo, whi);
    }
    group_wait(grp, 8u);

    const int wid = tid >> 5, lane = tid & 31;
    const int kq     = wid & 3;                  // k-quarter: 32 kpairs
    const int bhalf  = (wid >> 2) & 1;
    const int chalf  = wid >> 3;
    const int bgroup = lane >> 4;
    const int cg     = lane & 15;
    const int c0     = chalf * 64 + 2 * cg;      // cols c0, c0+1, c0+32, c0+33
    const int bb2    = bhalf * 8 + bgroup * 4;   // batches bb2..bb2+3
    const int kp0    = kq * 32;

    const ull* wrow0 = wq + kp0 * WST + c0;
    const ull* wrow1 = wrow0 + 32;
    const ull* hrow  = hq + kp0 * HST + bb2;
    float* zw = zs + kq * (128 * 17);

    int colg[4];
#pragma unroll
    for (int i = 0; i < 4; i++) {
        int c = c0 + (i & 1) + (i >> 1) * 32;
        colg[i] = (c >> 5) * 256 + jbase + (c & 31);
    }

    // preload xz for t=0 (kq==3 warps own xz)
    float xzc[4][4];   // [i: col][j: batch]
    if (kq == 3) {
#pragma unroll
        for (int j = 0; j < 4; j++) {
            const float* row = &g_xz[((size_t)(bbase + bb2 + j)) * 1024];
#pragma unroll
            for (int i = 0; i < 4; i++) xzc[i][j] = __ldcg(row + colg[i]);
        }
    }

    for (int t = 0; t < 512; t++) {
        const int par = t & 1;
        // h tile: coalesced LDG from L2, transposed to k-pair-major hq
        const float4* hsrc = (const float4*)&g_h[par][bbase][0];  // 1024 float4
#pragma unroll
        for (int u = 0; u < 2; u++) {
            int i = tid + u * 512;
            float4 v = __ldcg(hsrc + i);
            int b = i >> 6, q = i & 63;
            hq[(2 * q) * HST + b]     = pack2(v.x, v.y);
            hq[(2 * q + 1) * HST + b] = pack2(v.z, v.w);
        }
        __syncthreads();

        ull acc2[4][4];   // [j: batch][i: col]
#pragma unroll
        for (int j = 0; j < 4; j++)
#pragma unroll
            for (int i = 0; i < 4; i++) acc2[j][i] = 0ull;

#pragma unroll 4
        for (int kk = 0; kk < 32; kk++) {
            ulonglong2 wv0 = *(const ulonglong2*)(wrow0 + kk * WST);  // cols c0,c0+1
            ulonglong2 wv1 = *(const ulonglong2*)(wrow1 + kk * WST);  // cols +32,+33
            ulonglong2 hv0 = *(const ulonglong2*)(hrow + kk * HST);      // b, b+1
            ulonglong2 hv1 = *(const ulonglong2*)(hrow + kk * HST + 2);  // b+2, b+3
            ull hv[4] = {hv0.x, hv0.y, hv1.x, hv1.y};
#pragma unroll
            for (int j = 0; j < 4; j++) {
                acc2[j][0] = fma2(hv[j], wv0.x, acc2[j][0]);
                acc2[j][1] = fma2(hv[j], wv0.y, acc2[j][1]);
                acc2[j][2] = fma2(hv[j], wv1.x, acc2[j][2]);
                acc2[j][3] = fma2(hv[j], wv1.y, acc2[j][3]);
            }
        }

        const int cset[4] = {c0, c0 + 1, c0 + 32, c0 + 33};
        if (kq != 3) {
#pragma unroll
            for (int i = 0; i < 4; i++)
#pragma unroll
                for (int j = 0; j < 4; j++)
                    zw[cset[i] * 17 + bb2 + j] = lo32(acc2[j][i]) + hi32(acc2[j][i]);
        } else {
#pragma unroll
            for (int i = 0; i < 4; i++)
#pragma unroll
                for (int j = 0; j < 4; j++)
                    zw[cset[i] * 17 + bb2 + j] =
                        lo32(acc2[j][i]) + hi32(acc2[j][i]) + xzc[i][j];
            if (t < 511) {   // prefetch next xz off the critical path
#pragma unroll
                for (int j = 0; j < 4; j++) {
                    const float* row =
                        &g_xz[((size_t)((t + 1) * 256 + bbase + bb2 + j)) * 1024];
#pragma unroll
                    for (int i = 0; i < 4; i++) xzc[i][j] = __ldcg(row + colg[i]);
                }
            }
        }
        __syncthreads();

        // gates: 512 (b,j) pairs, 1 per thread; sum 4 k-quarter partials
        {
            int bb = tid >> 5, jj = tid & 31;
            float zi = 0.f, zf = 0.f, zg = 0.f, zo = 0.f;
#pragma unroll
            for (int q = 0; q < 4; q++) {
                const float* zq = zs + q * (128 * 17);
                zi += zq[(jj)      * 17 + bb];
                zf += zq[(32 + jj) * 17 + bb];
                zg += zq[(64 + jj) * 17 + bb];
                zo += zq[(96 + jj) * 17 + bb];
            }
            float cn = sigf(zf) * c_s[tid] + sigf(zi) * tanhfast(zg);
            c_s[tid] = cn;
            g_h[par ^ 1][bbase + bb][jbase + jj] = sigf(zo) * tanhfast(cn);
        }
        if (t < 511) group_wait(grp, 8u * (unsigned)(t + 2));
    }
    // final h in g_h[0] (512 even); kernel boundary syncs before head
}

// ---------------- MLP head ---------------------------------------------------
__global__ void __launch_bounds__(256)
head_kernel(const float* __restrict__ w1, const float* __restrict__ b1,
            const float* __restrict__ w2, const float* __restrict__ b2,
            float* __restrict__ out) {
    __shared__ float hs[256];
    __shared__ float ys[100];
    const int b = blockIdx.x, tid = threadIdx.x;
    hs[tid] = g_h[0][b][tid];
    __syncthreads();
    if (tid < 100) {
        float a = b1[tid];
#pragma unroll 4
        for (int k = 0; k < 256; k++) a = fmaf(hs[k], w1[k * 100 + tid], a);
        ys[tid] = fmaxf(a, 0.f);
    }
    __syncthreads();
    if (tid == 0) {
        float s = b2[0];
        for (int j = 0; j < 100; j++) s = fmaf(ys[j], w2[j], s);
        out[b] = s;
    }
}

// ---------------- launch ------------------------------------------------------
extern "C" void kernel_launch(void* const* d_in, const int* in_sizes, int n_in,
                              void* d_out, int out_size) {
    const float* x    = (const float*)d_in[0];
    const float* kern = (const float*)d_in[1];
    const float* rk   = (const float*)d_in[2];
    const float* w1   = (const float*)d_in[3];
    const float* b1   = (const float*)d_in[4];
    const float* w2   = (const float*)d_in[5];
    const float* b2   = (const float*)d_in[6];
    float* out = (float*)d_out;

    const int smem_bytes = 128 * WST * 8 + 128 * HST * 8
                         + 4 * 128 * 17 * 4 + 512 * 4;   // 188416
    cudaFuncSetAttribute(lstm_kernel, cudaFuncAttributeMaxDynamicSharedMemorySize,
                         smem_bytes);

    // order keeps ncu's capture (4th launch of cycle) on lstm_kernel
    reset_kernel<<<1, 16>>>();
    dim3 gg(8, 1024);
    xz_gemm_kernel<<<gg, 256>>>(x, kern);
    dummy_kernel<<<1, 1>>>();
    lstm_kernel<<<128, 512, smem_bytes>>>(rk);
    head_kernel<<<256, 256>>>(w1, b1, w2, b2, out);
}

// round 9
// speedup vs baseline: 1.2431x; 1.2431x over previous
#include <cuda_runtime.h>
#include <cstdint>

// ---------------------------------------------------------------------------
// MyModel_87522843559014: LSTM(B=256,T=512,F=128,H=256) + MLP head
//   reset -> xz_gemm -> dummy -> lstm (ncu captures 4th launch) -> head
//   lstm: 128 persistent blocks (16 groups x 8), recurrent GEMM via
//   mma.sync m16n8k8 tf32 (baseline PTX, works on compute_103 — tcgen05
//   is 'a'-gated and unavailable in this toolchain). Operands staged in
//   smem in fragment order; A (weights) built once, B (h) per step.
// ---------------------------------------------------------------------------

typedef unsigned long long ull;

__device__ float g_xz[512u * 256u * 1024u];   // [T][B][4H] fp32
__device__ float g_h[2][256][256];            // double-buffered hidden state
__device__ unsigned g_cnt[16 * 32];           // per-group counters, 128B apart

__global__ void reset_kernel() {
    if (threadIdx.x < 16) g_cnt[threadIdx.x * 32] = 0u;
}
__global__ void dummy_kernel() {}

// ---------------- f32x2 helpers (xz gemm) -------------------------------------
__device__ __forceinline__ ull fma2(ull a, ull b, ull c) {
    ull d;
    asm("fma.rn.f32x2 %0, %1, %2, %3;" : "=l"(d) : "l"(a), "l"(b), "l"(c));
    return d;
}
__device__ __forceinline__ ull dup2(float x) {
    ull r;
    asm("mov.b64 %0, {%1, %1};" : "=l"(r) : "f"(x));
    return r;
}
__device__ __forceinline__ float lo32(ull v) { return __uint_as_float((unsigned)v); }
__device__ __forceinline__ float hi32(ull v) { return __uint_as_float((unsigned)(v >> 32)); }

// ---------------- per-group barrier (8 blocks, padded counter) ----------------
__device__ __forceinline__ void group_wait(int grp, unsigned target) {
    __threadfence();
    __syncthreads();
    if (threadIdx.x == 0) {
        unsigned* ctr = &g_cnt[grp * 32];
        atomicAdd(ctr, 1u);
        unsigned v;
        do {
            asm volatile("ld.global.acquire.gpu.u32 %0, [%1];"
                         : "=r"(v) : "l"(ctr) : "memory");
        } while (v < target);
    }
    __syncthreads();
}

// ---------------- input projection GEMM (f32x2, unchanged) --------------------
__global__ void __launch_bounds__(256, 2)
xz_gemm_kernel(const float* __restrict__ x, const float* __restrict__ kern) {
    __shared__ float As[8][132];
    __shared__ float Bs[8][132];

    const int tid = threadIdx.x;
    const int nb = blockIdx.x;
    const int mb = blockIdx.y;
    const int m0 = mb * 128, n0 = nb * 128;

    const int lrow = tid >> 1;
    const int lk4  = (tid & 1) * 4;
    const int m    = m0 + lrow;
    const int tt   = m >> 8;
    const int bb   = m & 255;
    const float* xrow = x + ((size_t)bb * 512 + tt) * 128;

    const int bk = tid >> 5;
    const int bn = (tid & 31) * 4;

    const int tm = (tid >> 4) * 8;
    const int tn = (tid & 15) * 8;

    ull acc2[4][8];
#pragma unroll
    for (int i = 0; i < 4; i++)
#pragma unroll
        for (int j = 0; j < 8; j++) acc2[i][j] = 0ull;

    for (int k0 = 0; k0 < 128; k0 += 8) {
        float4 av = *(const float4*)(xrow + k0 + lk4);
        float4 bv = *(const float4*)(kern + (size_t)(k0 + bk) * 1024 + n0 + bn);
        __syncthreads();
        As[lk4 + 0][lrow] = av.x;
        As[lk4 + 1][lrow] = av.y;
        As[lk4 + 2][lrow] = av.z;
        As[lk4 + 3][lrow] = av.w;
        *(float4*)&Bs[bk][bn] = bv;
        __syncthreads();
#pragma unroll
        for (int kk = 0; kk < 8; kk++) {
            ulonglong2 a0 = *(const ulonglong2*)&As[kk][tm];
            ulonglong2 a1 = *(const ulonglong2*)&As[kk][tm + 4];
            ull ap[4] = {a0.x, a0.y, a1.x, a1.y};
            float4 b0 = *(const float4*)&Bs[kk][tn];
            float4 b1 = *(const float4*)&Bs[kk][tn + 4];
            {
                ull bd0 = dup2(b0.x), bd1 = dup2(b0.y), bd2 = dup2(b0.z), bd3 = dup2(b0.w);
#pragma unroll
                for (int i = 0; i < 4; i++) {
                    acc2[i][0] = fma2(ap[i], bd0, acc2[i][0]);
                    acc2[i][1] = fma2(ap[i], bd1, acc2[i][1]);
                    acc2[i][2] = fma2(ap[i], bd2, acc2[i][2]);
                    acc2[i][3] = fma2(ap[i], bd3, acc2[i][3]);
                }
            }
            {
                ull bd4 = dup2(b1.x), bd5 = dup2(b1.y), bd6 = dup2(b1.z), bd7 = dup2(b1.w);
#pragma unroll
                for (int i = 0; i < 4; i++) {
                    acc2[i][4] = fma2(ap[i], bd4, acc2[i][4]);
                    acc2[i][5] = fma2(ap[i], bd5, acc2[i][5]);
                    acc2[i][6] = fma2(ap[i], bd6, acc2[i][6]);
                    acc2[i][7] = fma2(ap[i], bd7, acc2[i][7]);
                }
            }
        }
    }

#pragma unroll
    for (int i2 = 0; i2 < 4; i2++) {
        float* d0 = g_xz + (size_t)(m0 + tm + 2 * i2) * 1024 + n0 + tn;
        float* d1 = d0 + 1024;
        *(float4*)(d0 + 0) = make_float4(lo32(acc2[i2][0]), lo32(acc2[i2][1]),
                                         lo32(acc2[i2][2]), lo32(acc2[i2][3]));
        *(float4*)(d0 + 4) = make_float4(lo32(acc2[i2][4]), lo32(acc2[i2][5]),
                                         lo32(acc2[i2][6]), lo32(acc2[i2][7]));
        *(float4*)(d1 + 0) = make_float4(hi32(acc2[i2][0]), hi32(acc2[i2][1]),
                                         hi32(acc2[i2][2]), hi32(acc2[i2][3]));
        *(float4*)(d1 + 4) = make_float4(hi32(acc2[i2][4]), hi32(acc2[i2][5]),
                                         hi32(acc2[i2][6]), hi32(acc2[i2][7]));
    }
}

// ---------------- fast activations -------------------------------------------
__device__ __forceinline__ float sigf(float x)     { return 1.f / (1.f + __expf(-x)); }
__device__ __forceinline__ float tanhfast(float x) { return 2.f / (1.f + __expf(-2.f * x)) - 1.f; }

// ---------------- tf32 mma helpers --------------------------------------------
__device__ __forceinline__ uint32_t to_tf32(float f) {
    uint32_t u;
    asm("cvt.rna.tf32.f32 %0, %1;" : "=r"(u) : "f"(f));
    return u;
}
__device__ __forceinline__ void mma_tf32(float* c, const uint32_t* a,
                                         const uint32_t* b) {
    asm volatile(
        "mma.sync.aligned.m16n8k8.row.col.f32.tf32.tf32.f32 "
        "{%0,%1,%2,%3}, {%4,%5,%6,%7}, {%8,%9}, {%0,%1,%2,%3};"
        : "+f"(c[0]), "+f"(c[1]), "+f"(c[2]), "+f"(c[3])
        : "r"(a[0]), "r"(a[1]), "r"(a[2]), "r"(a[3]), "r"(b[0]), "r"(b[1]));
}

// smem layout (bytes):
//   AF  [0, 131072)      : A fragments, 8192 x uint4 (weights, built once)
//   BF  [131072, 147456) : B fragments, 2048 x uint2 (h tile, per step)
//   zs  [147456, 182272) : 4 x [128][17] f32 partials
//   c_s [182272, 184320) : [512] f32 cell state
#define SM_AF    0
#define SM_BF    131072
#define SM_ZS    147456
#define SM_CS    182272
#define SM_TOTAL 184320

// ---------------- persistent LSTM kernel (mma.sync tf32) ----------------------
// 16 groups x 8 blocks, 256 threads. Block: 16 batches (N) x 128 gate-cols (M),
// K=256. Warp wid: mh=wid>>2 (M half of 64), kq=wid&3 (K quarter of 64).
// Per warp: 4 m-tiles x 2 n-tiles x 8 k-mmas of m16n8k8; accum in registers.
// AF index: (mh*4+kq)*1024 + km*128 + i*32 + lane   (uint4)
// BF index: kq*512 + km*64 + j*32 + lane            (uint2)
__global__ void __launch_bounds__(256, 1)
lstm_kernel(const float* __restrict__ rkernel) {
    extern __shared__ char smem[];
    uint4*  AF  = (uint4*)(smem + SM_AF);
    uint2*  BF  = (uint2*)(smem + SM_BF);
    float*  zs  = (float*)(smem + SM_ZS);
    float*  c_s = (float*)(smem + SM_CS);

    const int tid = threadIdx.x;
    const int wid = tid >> 5, lane = tid & 31;
    const int grp = blockIdx.x >> 3;    // 0..15
    const int jt  = blockIdx.x & 7;     // 0..7
    const int bbase = grp * 16, jbase = jt * 32;
    const int gid = lane >> 2, tig = lane & 3;

    // init c=0, h0 slice = 0
    for (int p = tid; p < 512; p += 256) {
        int bb = p >> 5, jj = p & 31;
        c_s[p] = 0.f;
        g_h[0][bbase + bb][jbase + jj] = 0.f;
    }
    // build A fragments once: A[m][k] = rkernel[k][colg(m)], tf32
    for (int idx = tid; idx < 8192; idx += 256) {
        int ln = idx & 31, t2 = idx >> 5;
        int i  = t2 & 3, km = (t2 >> 2) & 7, kqz = (t2 >> 5) & 3, mhz = t2 >> 7;
        int g2 = ln >> 2, t4 = ln & 3;
        int M0 = mhz * 64 + i * 16, K0 = kqz * 64 + km * 8;
        int mr0 = M0 + g2, mr1 = M0 + 8 + g2;
        int col0 = (mr0 >> 5) * 256 + jbase + (mr0 & 31);
        int col1 = (mr1 >> 5) * 256 + jbase + (mr1 & 31);
        uint4 v;
        v.x = to_tf32(rkernel[(K0 + t4) * 1024 + col0]);
        v.y = to_tf32(rkernel[(K0 + t4) * 1024 + col1]);
        v.z = to_tf32(rkernel[(K0 + t4 + 4) * 1024 + col0]);
        v.w = to_tf32(rkernel[(K0 + t4 + 4) * 1024 + col1]);
        AF[idx] = v;
    }
    group_wait(grp, 8u);

    const int mh = wid >> 2, kq = wid & 3;
    const int Mbase = mh * 64;
    const uint4* afp = AF + (mh * 4 + kq) * 1024 + lane;
    const uint2* bfp = BF + kq * 512 + lane;
    float* zq = zs + kq * (128 * 17);

    // xz prefetch registers (gate phase): [pp*4 + gate]
    float xzp[8], xzn[8];
#pragma unroll
    for (int pp = 0; pp < 2; pp++) {
        int p = tid + pp * 256;
        int bb = p >> 5, jj = p & 31;
        size_t base = ((size_t)(bbase + bb)) * 1024 + jbase + jj;
#pragma unroll
        for (int g = 0; g < 4; g++) xzp[pp * 4 + g] = __ldcg(&g_xz[base + g * 256]);
    }

    for (int t = 0; t < 512; t++) {
        const int par = t & 1;

        // B fragments: h(t) from L2, tf32, fragment order
#pragma unroll
        for (int u = 0; u < 8; u++) {
            int idx = tid + u * 256;
            int t2 = idx >> 5;
            int j = t2 & 1, km = (t2 >> 1) & 7, kqz = t2 >> 4;
            int n = j * 8 + gid;
            int k0 = kqz * 64 + km * 8 + tig;
            uint2 v;
            v.x = to_tf32(__ldcg(&g_h[par][bbase + n][k0]));
            v.y = to_tf32(__ldcg(&g_h[par][bbase + n][k0 + 4]));
            BF[idx] = v;
        }
        __syncthreads();

        // 64 MMAs, accumulators in registers
        float cacc[4][2][4];
#pragma unroll
        for (int i = 0; i < 4; i++)
#pragma unroll
            for (int j = 0; j < 2; j++)
#pragma unroll
                for (int r = 0; r < 4; r++) cacc[i][j][r] = 0.f;

#pragma unroll
        for (int km = 0; km < 8; km++) {
            uint32_t a[4][4], b[2][2];
#pragma unroll
            for (int i = 0; i < 4; i++) {
                uint4 av = afp[km * 128 + i * 32];
                a[i][0] = av.x; a[i][1] = av.y; a[i][2] = av.z; a[i][3] = av.w;
            }
#pragma unroll
            for (int j = 0; j < 2; j++) {
                uint2 bv = bfp[km * 64 + j * 32];
                b[j][0] = bv.x; b[j][1] = bv.y;
            }
#pragma unroll
            for (int i = 0; i < 4; i++)
#pragma unroll
                for (int j = 0; j < 2; j++)
                    mma_tf32(cacc[i][j], a[i], b[j]);
        }

        // write partials: c0:(m,n) c1:(m,n+1) c2:(m+8,n) c3:(m+8,n+1)
#pragma unroll
        for (int i = 0; i < 4; i++) {
            int m0 = Mbase + i * 16 + gid;
#pragma unroll
            for (int j = 0; j < 2; j++) {
                int n0 = j * 8 + tig * 2;
                zq[m0 * 17 + n0]           = cacc[i][j][0];
                zq[m0 * 17 + n0 + 1]       = cacc[i][j][1];
                zq[(m0 + 8) * 17 + n0]     = cacc[i][j][2];
                zq[(m0 + 8) * 17 + n0 + 1] = cacc[i][j][3];
            }
        }

        // prefetch next xz (independent of h -> off critical path)
        if (t < 511) {
#pragma unroll
            for (int pp = 0; pp < 2; pp++) {
                int p = tid + pp * 256;
                int bb = p >> 5, jj = p & 31;
                size_t base = ((size_t)((t + 1) * 256 + bbase + bb)) * 1024
                            + jbase + jj;
#pragma unroll
                for (int g = 0; g < 4; g++)
                    xzn[pp * 4 + g] = __ldcg(&g_xz[base + g * 256]);
            }
        }
        __syncthreads();

        // gates: 512 (b,j) pairs, 2 per thread; sum 4 k-quarter partials + xz
#pragma unroll
        for (int pp = 0; pp < 2; pp++) {
            int p = tid + pp * 256;
            int bb = p >> 5, jj = p & 31;
            float zi = xzp[pp * 4 + 0], zf = xzp[pp * 4 + 1];
            float zg = xzp[pp * 4 + 2], zo = xzp[pp * 4 + 3];
#pragma unroll
            for (int q = 0; q < 4; q++) {
                const float* zb = zs + q * (128 * 17);
                zi += zb[(jj)      * 17 + bb];
                zf += zb[(32 + jj) * 17 + bb];
                zg += zb[(64 + jj) * 17 + bb];
                zo += zb[(96 + jj) * 17 + bb];
            }
            float cn = sigf(zf) * c_s[p] + sigf(zi) * tanhfast(zg);
            c_s[p] = cn;
            g_h[par ^ 1][bbase + bb][jbase + jj] = sigf(zo) * tanhfast(cn);
        }
#pragma unroll
        for (int r = 0; r < 8; r++) xzp[r] = xzn[r];

        if (t < 511) group_wait(grp, 8u * (unsigned)(t + 2));
    }
    // final h in g_h[0] (512 even); kernel boundary syncs before head
}

// ---------------- MLP head ---------------------------------------------------
__global__ void __launch_bounds__(256)
head_kernel(const float* __restrict__ w1, const float* __restrict__ b1,
            const float* __restrict__ w2, const float* __restrict__ b2,
            float* __restrict__ out) {
    __shared__ float hs[256];
    __shared__ float ys[100];
    const int b = blockIdx.x, tid = threadIdx.x;
    hs[tid] = g_h[0][b][tid];
    __syncthreads();
    if (tid < 100) {
        float a = b1[tid];
#pragma unroll 4
        for (int k = 0; k < 256; k++) a = fmaf(hs[k], w1[k * 100 + tid], a);
        ys[tid] = fmaxf(a, 0.f);
    }
    __syncthreads();
    if (tid == 0) {
        float s = b2[0];
        for (int j = 0; j < 100; j++) s = fmaf(ys[j], w2[j], s);
        out[b] = s;
    }
}

// ---------------- launch ------------------------------------------------------
extern "C" void kernel_launch(void* const* d_in, const int* in_sizes, int n_in,
                              void* d_out, int out_size) {
    const float* x    = (const float*)d_in[0];
    const float* kern = (const float*)d_in[1];
    const float* rk   = (const float*)d_in[2];
    const float* w1   = (const float*)d_in[3];
    const float* b1   = (const float*)d_in[4];
    const float* w2   = (const float*)d_in[5];
    const float* b2   = (const float*)d_in[6];
    float* out = (float*)d_out;

    cudaFuncSetAttribute(lstm_kernel, cudaFuncAttributeMaxDynamicSharedMemorySize,
                         SM_TOTAL);

    // order keeps ncu's capture (4th launch of cycle) on lstm_kernel
    reset_kernel<<<1, 16>>>();
    dim3 gg(8, 1024);
    xz_gemm_kernel<<<gg, 256>>>(x, kern);
    dummy_kernel<<<1, 1>>>();
    lstm_kernel<<<128, 256, SM_TOTAL>>>(rk);
    head_kernel<<<256, 256>>>(w1, b1, w2, b2, out);
}

// round 10
// speedup vs baseline: 1.2819x; 1.0312x over previous
#include <cuda_runtime.h>
#include <cstdint>

// ---------------------------------------------------------------------------
// MyModel_87522843559014: LSTM(B=256,T=512,F=128,H=256) + MLP head
//   reset -> xz_gemm -> dummy -> lstm (ncu captures 4th launch) -> head
//   lstm: 128 persistent blocks (16 groups x 8), mma.sync m16n8k8 tf32.
//   R10: weight fragments live in REGISTERS (128/thread, loaded once);
//        flag-array group barrier (no atomics, padded lines).
// ---------------------------------------------------------------------------

typedef unsigned long long ull;

__device__ float g_xz[512u * 256u * 1024u];   // [T][B][4H] fp32
__device__ float g_h[2][256][256];            // double-buffered hidden state
__device__ unsigned g_flag[16 * 8 * 32];      // per-block flags, 128B apart

__global__ void reset_kernel() {
    if (threadIdx.x < 128) g_flag[threadIdx.x * 32] = 0u;
}
__global__ void dummy_kernel() {}

// ---------------- f32x2 helpers (xz gemm) -------------------------------------
__device__ __forceinline__ ull fma2(ull a, ull b, ull c) {
    ull d;
    asm("fma.rn.f32x2 %0, %1, %2, %3;" : "=l"(d) : "l"(a), "l"(b), "l"(c));
    return d;
}
__device__ __forceinline__ ull dup2(float x) {
    ull r;
    asm("mov.b64 %0, {%1, %1};" : "=l"(r) : "f"(x));
    return r;
}
__device__ __forceinline__ float lo32(ull v) { return __uint_as_float((unsigned)v); }
__device__ __forceinline__ float hi32(ull v) { return __uint_as_float((unsigned)(v >> 32)); }

// ---------------- flag barrier (8 blocks/group, no atomics) -------------------
__device__ __forceinline__ void flag_sync(int grp, int jt, unsigned id) {
    __threadfence();               // each thread publishes its global stores
    __syncthreads();
    if (threadIdx.x == 0) {
        asm volatile("st.release.gpu.global.u32 [%0], %1;"
                     :: "l"(&g_flag[(grp * 8 + jt) * 32]), "r"(id) : "memory");
    }
    if (threadIdx.x < 8) {
        const unsigned* f = &g_flag[(grp * 8 + (int)threadIdx.x) * 32];
        unsigned v;
        do {
            asm volatile("ld.acquire.gpu.global.u32 %0, [%1];"
                         : "=r"(v) : "l"(f) : "memory");
        } while (v < id);
    }
    __syncthreads();
}

// ---------------- input projection GEMM (f32x2, unchanged) --------------------
__global__ void __launch_bounds__(256, 2)
xz_gemm_kernel(const float* __restrict__ x, const float* __restrict__ kern) {
    __shared__ float As[8][132];
    __shared__ float Bs[8][132];

    const int tid = threadIdx.x;
    const int nb = blockIdx.x;
    const int mb = blockIdx.y;
    const int m0 = mb * 128, n0 = nb * 128;

    const int lrow = tid >> 1;
    const int lk4  = (tid & 1) * 4;
    const int m    = m0 + lrow;
    const int tt   = m >> 8;
    const int bb   = m & 255;
    const float* xrow = x + ((size_t)bb * 512 + tt) * 128;

    const int bk = tid >> 5;
    const int bn = (tid & 31) * 4;

    const int tm = (tid >> 4) * 8;
    const int tn = (tid & 15) * 8;

    ull acc2[4][8];
#pragma unroll
    for (int i = 0; i < 4; i++)
#pragma unroll
        for (int j = 0; j < 8; j++) acc2[i][j] = 0ull;

    for (int k0 = 0; k0 < 128; k0 += 8) {
        float4 av = *(const float4*)(xrow + k0 + lk4);
        float4 bv = *(const float4*)(kern + (size_t)(k0 + bk) * 1024 + n0 + bn);
        __syncthreads();
        As[lk4 + 0][lrow] = av.x;
        As[lk4 + 1][lrow] = av.y;
        As[lk4 + 2][lrow] = av.z;
        As[lk4 + 3][lrow] = av.w;
        *(float4*)&Bs[bk][bn] = bv;
        __syncthreads();
#pragma unroll
        for (int kk = 0; kk < 8; kk++) {
            ulonglong2 a0 = *(const ulonglong2*)&As[kk][tm];
            ulonglong2 a1 = *(const ulonglong2*)&As[kk][tm + 4];
            ull ap[4] = {a0.x, a0.y, a1.x, a1.y};
            float4 b0 = *(const float4*)&Bs[kk][tn];
            float4 b1 = *(const float4*)&Bs[kk][tn + 4];
            {
                ull bd0 = dup2(b0.x), bd1 = dup2(b0.y), bd2 = dup2(b0.z), bd3 = dup2(b0.w);
#pragma unroll
                for (int i = 0; i < 4; i++) {
                    acc2[i][0] = fma2(ap[i], bd0, acc2[i][0]);
                    acc2[i][1] = fma2(ap[i], bd1, acc2[i][1]);
                    acc2[i][2] = fma2(ap[i], bd2, acc2[i][2]);
                    acc2[i][3] = fma2(ap[i], bd3, acc2[i][3]);
                }
            }
            {
                ull bd4 = dup2(b1.x), bd5 = dup2(b1.y), bd6 = dup2(b1.z), bd7 = dup2(b1.w);
#pragma unroll
                for (int i = 0; i < 4; i++) {
                    acc2[i][4] = fma2(ap[i], bd4, acc2[i][4]);
                    acc2[i][5] = fma2(ap[i], bd5, acc2[i][5]);
                    acc2[i][6] = fma2(ap[i], bd6, acc2[i][6]);
                    acc2[i][7] = fma2(ap[i], bd7, acc2[i][7]);
                }
            }
        }
    }

#pragma unroll
    for (int i2 = 0; i2 < 4; i2++) {
        float* d0 = g_xz + (size_t)(m0 + tm + 2 * i2) * 1024 + n0 + tn;
        float* d1 = d0 + 1024;
        *(float4*)(d0 + 0) = make_float4(lo32(acc2[i2][0]), lo32(acc2[i2][1]),
                                         lo32(acc2[i2][2]), lo32(acc2[i2][3]));
        *(float4*)(d0 + 4) = make_float4(lo32(acc2[i2][4]), lo32(acc2[i2][5]),
                                         lo32(acc2[i2][6]), lo32(acc2[i2][7]));
        *(float4*)(d1 + 0) = make_float4(hi32(acc2[i2][0]), hi32(acc2[i2][1]),
                                         hi32(acc2[i2][2]), hi32(acc2[i2][3]));
        *(float4*)(d1 + 4) = make_float4(hi32(acc2[i2][4]), hi32(acc2[i2][5]),
                                         hi32(acc2[i2][6]), hi32(acc2[i2][7]));
    }
}

// ---------------- fast activations -------------------------------------------
__device__ __forceinline__ float sigf(float x)     { return 1.f / (1.f + __expf(-x)); }
__device__ __forceinline__ float tanhfast(float x) { return 2.f / (1.f + __expf(-2.f * x)) - 1.f; }

// ---------------- tf32 mma helpers --------------------------------------------
__device__ __forceinline__ uint32_t to_tf32(float f) {
    uint32_t u;
    asm("cvt.rna.tf32.f32 %0, %1;" : "=r"(u) : "f"(f));
    return u;
}
__device__ __forceinline__ void mma_tf32(float* c, const uint32_t* a,
                                         const uint32_t* b) {
    asm volatile(
        "mma.sync.aligned.m16n8k8.row.col.f32.tf32.tf32.f32 "
        "{%0,%1,%2,%3}, {%4,%5,%6,%7}, {%8,%9}, {%0,%1,%2,%3};"
        : "+f"(c[0]), "+f"(c[1]), "+f"(c[2]), "+f"(c[3])
        : "r"(a[0]), "r"(a[1]), "r"(a[2]), "r"(a[3]), "r"(b[0]), "r"(b[1]));
}

// smem layout (bytes). AF (one-time A staging, 131072B) ALIASES the loop-time
// regions; A is copied to registers before BF/zs/c_s are first written.
#define SM_BF    0         // 2048 x uint2 B fragments          16384
#define SM_ZS    16384     // 4 x [128][17] f32 partials        34816
#define SM_CS    51200     // [512] f32 cell state               2048
#define SM_TOTAL 131072    // = AF staging size (max of uses)

// ---------------- persistent LSTM kernel (mma.sync tf32, A in regs) -----------
// 16 groups x 8 blocks, 256 threads. Block: 16 batches (N) x 128 gate-cols (M),
// K=256. Warp wid: mh=wid>>2 (M half of 64), kq=wid&3 (K quarter of 64).
// areg[i][km] : uint4 A fragment (m-tile i, k-mma km) -- resident all 512 steps.
// BF index: kq*512 + km*64 + j*32 + lane  (uint2)
__global__ void __launch_bounds__(256, 1)
lstm_kernel(const float* __restrict__ rkernel) {
    extern __shared__ char smem[];
    uint4*  AF  = (uint4*)(smem);            // staging only (pre-loop)
    uint2*  BF  = (uint2*)(smem + SM_BF);
    float*  zs  = (float*)(smem + SM_ZS);
    float*  c_s = (float*)(smem + SM_CS);

    const int tid = threadIdx.x;
    const int wid = tid >> 5, lane = tid & 31;
    const int grp = blockIdx.x >> 3;    // 0..15
    const int jt  = blockIdx.x & 7;     // 0..7
    const int bbase = grp * 16, jbase = jt * 32;
    const int gid = lane >> 2, tig = lane & 3;

    // ---- stage A fragments in smem (fragment order), then copy to registers
    for (int idx = tid; idx < 8192; idx += 256) {
        int ln = idx & 31, t2 = idx >> 5;
        int i  = t2 & 3, km = (t2 >> 2) & 7, kqz = (t2 >> 5) & 3, mhz = t2 >> 7;
        int g2 = ln >> 2, t4 = ln & 3;
        int M0 = mhz * 64 + i * 16, K0 = kqz * 64 + km * 8;
        int mr0 = M0 + g2, mr1 = M0 + 8 + g2;
        int col0 = (mr0 >> 5) * 256 + jbase + (mr0 & 31);
        int col1 = (mr1 >> 5) * 256 + jbase + (mr1 & 31);
        uint4 v;
        v.x = to_tf32(rkernel[(K0 + t4) * 1024 + col0]);
        v.y = to_tf32(rkernel[(K0 + t4) * 1024 + col1]);
        v.z = to_tf32(rkernel[(K0 + t4 + 4) * 1024 + col0]);
        v.w = to_tf32(rkernel[(K0 + t4 + 4) * 1024 + col1]);
        AF[idx] = v;
    }
    __syncthreads();

    const int mh = wid >> 2, kq = wid & 3;
    const int Mbase = mh * 64;
    uint4 areg[4][8];
    {
        const uint4* afp = AF + (mh * 4 + kq) * 1024 + lane;
#pragma unroll
        for (int i = 0; i < 4; i++)
#pragma unroll
            for (int km = 0; km < 8; km++)
                areg[i][km] = afp[km * 128 + i * 32];
    }
    __syncthreads();   // AF region now reusable as BF/zs/c_s

    // init c=0, h0 slice = 0
    for (int p = tid; p < 512; p += 256) {
        int bb = p >> 5, jj = p & 31;
        c_s[p] = 0.f;
        g_h[0][bbase + bb][jbase + jj] = 0.f;
    }
    flag_sync(grp, jt, 1u);

    const uint2* bfp = BF + kq * 512 + lane;
    float* zq = zs + kq * (128 * 17);

    // xz prefetch registers (gate phase): [pp*4 + gate]
    float xzp[8], xzn[8];
#pragma unroll
    for (int pp = 0; pp < 2; pp++) {
        int p = tid + pp * 256;
        int bb = p >> 5, jj = p & 31;
        size_t base = ((size_t)(bbase + bb)) * 1024 + jbase + jj;
#pragma unroll
        for (int g = 0; g < 4; g++) xzp[pp * 4 + g] = __ldcg(&g_xz[base + g * 256]);
    }

    for (int t = 0; t < 512; t++) {
        const int par = t & 1;

        // B fragments: h(t) from L2, tf32, fragment order
#pragma unroll
        for (int u = 0; u < 8; u++) {
            int idx = tid + u * 256;
            int t2 = idx >> 5;
            int j = t2 & 1, km = (t2 >> 1) & 7, kqz = t2 >> 4;
            int n = j * 8 + gid;
            int k0 = kqz * 64 + km * 8 + tig;
            uint2 v;
            v.x = to_tf32(__ldcg(&g_h[par][bbase + n][k0]));
            v.y = to_tf32(__ldcg(&g_h[par][bbase + n][k0 + 4]));
            BF[idx] = v;
        }
        __syncthreads();

        // 64 MMAs, A operands from registers
        float cacc[4][2][4];
#pragma unroll
        for (int i = 0; i < 4; i++)
#pragma unroll
            for (int j = 0; j < 2; j++)
#pragma unroll
                for (int r = 0; r < 4; r++) cacc[i][j][r] = 0.f;

#pragma unroll
        for (int km = 0; km < 8; km++) {
            uint2 bv0 = bfp[km * 64];
            uint2 bv1 = bfp[km * 64 + 32];
            uint32_t b0[2] = {bv0.x, bv0.y};
            uint32_t b1[2] = {bv1.x, bv1.y};
#pragma unroll
            for (int i = 0; i < 4; i++) {
                uint32_t a[4] = {areg[i][km].x, areg[i][km].y,
                                 areg[i][km].z, areg[i][km].w};
                mma_tf32(cacc[i][0], a, b0);
                mma_tf32(cacc[i][1], a, b1);
            }
        }

        // write partials: c0:(m,n) c1:(m,n+1) c2:(m+8,n) c3:(m+8,n+1)
#pragma unroll
        for (int i = 0; i < 4; i++) {
            int m0 = Mbase + i * 16 + gid;
#pragma unroll
            for (int j = 0; j < 2; j++) {
                int n0 = j * 8 + tig * 2;
                zq[m0 * 17 + n0]           = cacc[i][j][0];
                zq[m0 * 17 + n0 + 1]       = cacc[i][j][1];
                zq[(m0 + 8) * 17 + n0]     = cacc[i][j][2];
                zq[(m0 + 8) * 17 + n0 + 1] = cacc[i][j][3];
            }
        }

        // prefetch next xz (independent of h -> off critical path)
        if (t < 511) {
#pragma unroll
            for (int pp = 0; pp < 2; pp++) {
                int p = tid + pp * 256;
                int bb = p >> 5, jj = p & 31;
                size_t base = ((size_t)((t + 1) * 256 + bbase + bb)) * 1024
                            + jbase + jj;
#pragma unroll
                for (int g = 0; g < 4; g++)
                    xzn[pp * 4 + g] = __ldcg(&g_xz[base + g * 256]);
            }
        }
        __syncthreads();

        // gates: 512 (b,j) pairs, 2 per thread; sum 4 k-quarter partials + xz
#pragma unroll
        for (int pp = 0; pp < 2; pp++) {
            int p = tid + pp * 256;
            int bb = p >> 5, jj = p & 31;
            float zi = xzp[pp * 4 + 0], zf = xzp[pp * 4 + 1];
            float zg = xzp[pp * 4 + 2], zo = xzp[pp * 4 + 3];
#pragma unroll
            for (int q = 0; q < 4; q++) {
                const float* zb = zs + q * (128 * 17);
                zi += zb[(jj)      * 17 + bb];
                zf += zb[(32 + jj) * 17 + bb];
                zg += zb[(64 + jj) * 17 + bb];
                zo += zb[(96 + jj) * 17 + bb];
            }
            float cn = sigf(zf) * c_s[p] + sigf(zi) * tanhfast(zg);
            c_s[p] = cn;
            g_h[par ^ 1][bbase + bb][jbase + jj] = sigf(zo) * tanhfast(cn);
        }
#pragma unroll
        for (int r = 0; r < 8; r++) xzp[r] = xzn[r];

        if (t < 511) flag_sync(grp, jt, (unsigned)(t + 2));
    }
    // final h in g_h[0] (512 even); kernel boundary syncs before head
}

// ---------------- MLP head ---------------------------------------------------
__global__ void __launch_bounds__(256)
head_kernel(const float* __restrict__ w1, const float* __restrict__ b1,
            const float* __restrict__ w2, const float* __restrict__ b2,
            float* __restrict__ out) {
    __shared__ float hs[256];
    __shared__ float ys[100];
    const int b = blockIdx.x, tid = threadIdx.x;
    hs[tid] = g_h[0][b][tid];
    __syncthreads();
    if (tid < 100) {
        float a = b1[tid];
#pragma unroll 4
        for (int k = 0; k < 256; k++) a = fmaf(hs[k], w1[k * 100 + tid], a);
        ys[tid] = fmaxf(a, 0.f);
    }
    __syncthreads();
    if (tid == 0) {
        float s = b2[0];
        for (int j = 0; j < 100; j++) s = fmaf(ys[j], w2[j], s);
        out[b] = s;
    }
}

// ---------------- launch ------------------------------------------------------
extern "C" void kernel_launch(void* const* d_in, const int* in_sizes, int n_in,
                              void* d_out, int out_size) {
    const float* x    = (const float*)d_in[0];
    const float* kern = (const float*)d_in[1];
    const float* rk   = (const float*)d_in[2];
    const float* w1   = (const float*)d_in[3];
    const float* b1   = (const float*)d_in[4];
    const float* w2   = (const float*)d_in[5];
    const float* b2   = (const float*)d_in[6];
    float* out = (float*)d_out;

    cudaFuncSetAttribute(lstm_kernel, cudaFuncAttributeMaxDynamicSharedMemorySize,
                         SM_TOTAL);

    // order keeps ncu's capture (4th launch of cycle) on lstm_kernel
    reset_kernel<<<1, 128>>>();
    dim3 gg(8, 1024);
    xz_gemm_kernel<<<gg, 256>>>(x, kern);
    dummy_kernel<<<1, 1>>>();
    lstm_kernel<<<128, 256, SM_TOTAL>>>(rk);
    head_kernel<<<256, 256>>>(w1, b1, w2, b2, out);
}